// round 16
// baseline (speedup 1.0000x reference)
#include <cuda_runtime.h>
#include <cuda_bf16.h>
#include <cuda_fp16.h>
#include <math.h>
#include <stdint.h>

// ---------------- problem constants ----------------
#define BSZ   4
#define GHW   128
#define WS    16
#define TT    256            // tokens per window
#define NWIN  256
#define NH    16
#define HD    64
#define CD    1024
#define C3    3072
#define MTOT  65536          // NWIN * TT
#define QSCALE_E 0.180336880111120430f   // 0.125 * log2(e): scores in base-2 units

// GEMM tile config (HMMA, cp.async 3-stage, BK=32)
#define BM 128
#define BN 128
#define BK 32
#define KP 40                // padded row elems (20 words) -> conflict-free frag LDS
#define KPW 20
#define AH_E 0
#define BH_E (128 * KP)
#define STAGE_E (2 * 128 * KP)            // 10240 elems
#define STAGE_B (STAGE_E * 2)             // 20480 bytes
#define STAGE_W (STAGE_E / 2)             // 5120 words
#define NSTAGE 3
#define GEMM_SMEM (NSTAGE * STAGE_B)      // 61440 bytes dynamic

// flash-attention smem layout (halves)
#define SKP   72                          // K row stride (36 words)
#define VTP   264                         // Vt row stride (132 words)
#define ATTN_SMEM ((TT * SKP + HD * VTP) * 2)   // 70656 bytes

// ---------------- scratch (no allocation allowed) ----------------
__device__ __half g_Qh[(size_t)NWIN * NH * TT * HD];
__device__ __half g_Kh[(size_t)NWIN * NH * TT * HD];
__device__ __half g_Vh[(size_t)NWIN * NH * TT * HD];
__device__ __half g_xf[(size_t)MTOT * CD];   // x fp16, window order
__device__ __half g_of[(size_t)MTOT * CD];   // attention out fp16 (proj A)
__device__ __half g_wf[(size_t)C3 * CD];     // Wqkv fp16
__device__ __half g_wpf[(size_t)CD * CD];    // Wproj fp16
__device__ float g_cos[TT * 32];
__device__ float g_sin[TT * 32];
__device__ int   g_xrow[MTOT];

__device__ __forceinline__ int xrow_of_m(int m) {
    int win = m >> 8, t = m & 255;
    int b = win >> 6, wh = (win >> 3) & 7, ww = win & 7;
    int r = t >> 4, c = t & 15;
    return b * (GHW * GHW) + (wh * WS + r) * GHW + (ww * WS + c);
}

__device__ __forceinline__ void mma_fp16(float* c, const uint32_t* a, uint32_t b0, uint32_t b1) {
    asm volatile("mma.sync.aligned.m16n8k16.row.col.f32.f16.f16.f32 "
                 "{%0,%1,%2,%3}, {%4,%5,%6,%7}, {%8,%9}, {%0,%1,%2,%3};"
                 : "+f"(c[0]), "+f"(c[1]), "+f"(c[2]), "+f"(c[3])
                 : "r"(a[0]), "r"(a[1]), "r"(a[2]), "r"(a[3]), "r"(b0), "r"(b1));
}

__device__ __forceinline__ uint32_t smem_u32(const void* p) {
    uint32_t a;
    asm("{ .reg .u64 t; cvta.to.shared.u64 t, %1; cvt.u32.u64 %0, t; }" : "=r"(a) : "l"(p));
    return a;
}
__device__ __forceinline__ uint32_t packh2(float a, float b) {
    union { __half2 h; uint32_t u; } v;
    v.h = __floats2half2_rn(a, b);
    return v.u;
}

#define CP16(dst, src) \
    asm volatile("cp.async.cg.shared.global [%0], [%1], 16;" :: "r"(dst), "l"(src) : "memory")
#define CP_COMMIT() asm volatile("cp.async.commit_group;" ::: "memory")
#define CP_WAIT1()  asm volatile("cp.async.wait_group 1;" ::: "memory")
#define CP_WAIT0()  asm volatile("cp.async.wait_group 0;" ::: "memory")

// ---------------- init: rope table + gather map ----------------
__global__ void init_tables_kernel() {
    int i = blockIdx.x * 256 + threadIdx.x;
    if (i < MTOT) g_xrow[i] = xrow_of_m(i);
    if (i < TT * 32) {
        int t = i >> 5, j = i & 31;
        int r = t >> 4, c = t & 15;
        float inv = powf(10000.0f, -(float)j / 32.0f);
        float pos = (j < 16) ? (float)r : (float)c;
        g_cos[i] = cosf(pos * inv);
        g_sin[i] = sinf(pos * inv);
    }
}

// ---------------- conversion helpers ----------------
union U4F16 { uint4 u; __half h[8]; };

__device__ __forceinline__ void tof16(const float* v, U4F16& f) {
#pragma unroll
    for (int j = 0; j < 8; ++j) f.h[j] = __float2half(v[j]);
}

__global__ void __launch_bounds__(256) conv_x_kernel(const float* __restrict__ x) {
    int i = blockIdx.x * 256 + threadIdx.x;
    int e0 = i * 8;
    int m = e0 >> 10, k = e0 & 1023;
    int src = xrow_of_m(m);
    float v[8];
    const float4* sp = reinterpret_cast<const float4*>(x + (size_t)src * CD + k);
    float4 a = sp[0], b = sp[1];
    v[0]=a.x; v[1]=a.y; v[2]=a.z; v[3]=a.w; v[4]=b.x; v[5]=b.y; v[6]=b.z; v[7]=b.w;
    U4F16 f; tof16(v, f);
    reinterpret_cast<uint4*>(g_xf + (size_t)m * CD + k)[0] = f.u;
}

// both weight arrays in one launch
__global__ void __launch_bounds__(256) conv_w_kernel(const float* __restrict__ wqkv,
                                                     const float* __restrict__ wproj) {
    int i = blockIdx.x * 256 + threadIdx.x;
    size_t e0 = (size_t)i * 8;
    const float* src; __half* dst;
    if (e0 < (size_t)C3 * CD) { src = wqkv + e0; dst = g_wf + e0; }
    else { src = wproj + (e0 - (size_t)C3 * CD); dst = g_wpf + (e0 - (size_t)C3 * CD); }
    float v[8];
    const float4* sp = reinterpret_cast<const float4*>(src);
    float4 a = sp[0], b = sp[1];
    v[0]=a.x; v[1]=a.y; v[2]=a.z; v[3]=a.w; v[4]=b.x; v[5]=b.y; v[6]=b.z; v[7]=b.w;
    U4F16 f; tof16(v, f);
    reinterpret_cast<uint4*>(dst)[0] = f.u;
}

// ---------------- HMMA fp16 GEMM (BK=32, 3-stage, 1 barrier/chunk) ----------
// mode 0: QKV — A=g_xf, B=g_wf (3072 cols), epilogue RoPE(Q,K)+V -> g_Qh/g_Kh/g_Vh
// mode 1: proj — A=g_of, B=g_wpf, scatter rows via g_xrow -> out (fp32)
__global__ void __launch_bounds__(256) hmma_gemm_kernel(int mode, float* __restrict__ out) {
    extern __shared__ __half ts[];

    const char* Ap = (mode == 0) ? (const char*)g_xf : (const char*)g_of;
    const char* Bp = (mode == 0) ? (const char*)g_wf : (const char*)g_wpf;

    const int tid  = threadIdx.x;
    const int wid  = tid >> 5;
    const int lane = tid & 31;
    const int wm   = wid & 3;
    const int wn   = wid >> 2;
    const int grp  = lane >> 2;
    const int tig  = lane & 3;
    const int m0   = blockIdx.y * BM;
    const int n0   = blockIdx.x * BN;

    // staging map (proven): u = tid*2 + j ; row = u>>2, seg = (u&3)*8 elems (16B)
    const int u0 = tid * 2, u1 = tid * 2 + 1;
    const int r0s = u0 >> 2, s0s = (u0 & 3) * 8;
    const int r1s = u1 >> 2, s1s = (u1 & 3) * 8;
    const size_t gA0 = ((size_t)(m0 + r0s) * CD + s0s) * 2;   // byte offsets
    const size_t gA1 = ((size_t)(m0 + r1s) * CD + s1s) * 2;
    const size_t gB0 = ((size_t)(n0 + r0s) * CD + s0s) * 2;
    const size_t gB1 = ((size_t)(n0 + r1s) * CD + s1s) * 2;

    const uint32_t ts_u32 = smem_u32(ts);
    const uint32_t dAH0 = (uint32_t)(AH_E + r0s * KP + s0s) * 2;
    const uint32_t dAH1 = (uint32_t)(AH_E + r1s * KP + s1s) * 2;
    const uint32_t dBH0 = (uint32_t)(BH_E + r0s * KP + s0s) * 2;
    const uint32_t dBH1 = (uint32_t)(BH_E + r1s * KP + s1s) * 2;

    const uint32_t* s32 = reinterpret_cast<const uint32_t*>(ts);

    float C[2][8][4];
#pragma unroll
    for (int a = 0; a < 2; ++a)
#pragma unroll
        for (int n = 0; n < 8; ++n)
#pragma unroll
            for (int j = 0; j < 4; ++j) C[a][n][j] = 0.0f;

    const int NCH = CD / BK;   // 32

    // prologue: stages 0 and 1 in flight (separate commit groups)
    {
        const uint32_t sb0 = ts_u32;
        CP16(sb0 + dAH0, Ap + gA0); CP16(sb0 + dAH1, Ap + gA1);
        CP16(sb0 + dBH0, Bp + gB0); CP16(sb0 + dBH1, Bp + gB1);
        CP_COMMIT();
        const size_t k1 = (size_t)BK * 2;
        const uint32_t sb1 = ts_u32 + STAGE_B;
        CP16(sb1 + dAH0, Ap + gA0 + k1); CP16(sb1 + dAH1, Ap + gA1 + k1);
        CP16(sb1 + dBH0, Bp + gB0 + k1); CP16(sb1 + dBH1, Bp + gB1 + k1);
        CP_COMMIT();
    }

    int stage = 0;
#pragma unroll 1
    for (int c = 0; c < NCH; ++c) {
        if (c + 1 < NCH) { CP_WAIT1(); } else { CP_WAIT0(); }   // stage c retired
        __syncthreads();   // stage c visible; prev compute done (protects c+2 slot)

        if (c + 2 < NCH) {
            const size_t k2 = (size_t)(c + 2) * BK * 2;
            int st2 = stage + 2; if (st2 >= NSTAGE) st2 -= NSTAGE;
            const uint32_t sb = ts_u32 + (uint32_t)st2 * STAGE_B;
            CP16(sb + dAH0, Ap + gA0 + k2); CP16(sb + dAH1, Ap + gA1 + k2);
            CP16(sb + dBH0, Bp + gB0 + k2); CP16(sb + dBH1, Bp + gB1 + k2);
            CP_COMMIT();
        }

        const uint32_t sw = (uint32_t)stage * STAGE_W;
#pragma unroll
        for (int ks = 0; ks < 2; ++ks) {
            const int kw = ks * 8 + tig;
            uint32_t ah[2][4];
#pragma unroll
            for (int a = 0; a < 2; ++a) {
                const int r = wm * 32 + a * 16 + grp;
                ah[a][0] = s32[sw + (AH_E / 2) + (r    ) * KPW + kw    ];
                ah[a][1] = s32[sw + (AH_E / 2) + (r + 8) * KPW + kw    ];
                ah[a][2] = s32[sw + (AH_E / 2) + (r    ) * KPW + kw + 4];
                ah[a][3] = s32[sw + (AH_E / 2) + (r + 8) * KPW + kw + 4];
            }
#pragma unroll
            for (int nt = 0; nt < 8; ++nt) {
                const int nr = wn * 64 + nt * 8 + grp;
                uint32_t bh0 = s32[sw + (BH_E / 2) + nr * KPW + kw];
                uint32_t bh1 = s32[sw + (BH_E / 2) + nr * KPW + kw + 4];
#pragma unroll
                for (int a = 0; a < 2; ++a)
                    mma_fp16(C[a][nt], ah[a], bh0, bh1);
            }
        }
        if (++stage == NSTAGE) stage = 0;
    }

    // ---------------- epilogue ----------------
#pragma unroll
    for (int a = 0; a < 2; ++a) {
#pragma unroll
        for (int nt = 0; nt < 8; ++nt) {
            const int col = n0 + wn * 64 + nt * 8 + 2 * tig;
#pragma unroll
            for (int half = 0; half < 2; ++half) {
                const int row = m0 + wm * 32 + a * 16 + grp + half * 8;
                float v0 = C[a][nt][half * 2 + 0];
                float v1 = C[a][nt][half * 2 + 1];
                if (mode == 0) {
                    const int t = row & 255, win = row >> 8;
                    const int s = col >> 10;                 // 0=Q, 1=K, 2=V
                    const int h = (col & 1023) >> 6;
                    const int d = col & 63;                  // even
                    float o0, o1;
                    if (s < 2) {
                        const int p = d >> 1;
                        float cc = g_cos[t * 32 + p], ss = g_sin[t * 32 + p];
                        o0 = v0 * cc - v1 * ss;
                        o1 = v0 * ss + v1 * cc;
                        if (s == 0) { o0 *= QSCALE_E; o1 *= QSCALE_E; }
                    } else { o0 = v0; o1 = v1; }
                    __half* dst = (s == 0) ? g_Qh : (s == 1) ? g_Kh : g_Vh;
                    const size_t base = (((size_t)(win * NH + h)) * TT + t) * (size_t)HD + d;
                    *reinterpret_cast<uint32_t*>(dst + base) = packh2(o0, o1);
                } else {
                    const size_t orow = (size_t)g_xrow[row];
                    *reinterpret_cast<float2*>(out + orow * CD + col) = make_float2(v0, v1);
                }
            }
        }
    }
}

// ---------------- HMMA flash-attention: one CTA per (win, head), base-2 softmax ----------
__global__ void __launch_bounds__(256) attn_kernel() {
    extern __shared__ __half sma[];
    __half* sK  = sma;                    // [256][72]
    __half* sVt = sma + TT * SKP;         // [64][264]
    const uint32_t* sK32  = reinterpret_cast<const uint32_t*>(sK);
    const uint32_t* sVt32 = reinterpret_cast<const uint32_t*>(sVt);
    const uint32_t sK_u32 = smem_u32(sK);

    const int bx  = blockIdx.x;           // win*16 + h
    const int tid = threadIdx.x;
    const int wq  = tid >> 5;
    const int lane = tid & 31;
    const int grp = lane >> 2, tig = lane & 3;
    const size_t base = (size_t)bx * TT * HD;

    // K via cp.async (8 x 16B per thread), V transpose scalar in the shadow
    for (int u = tid; u < TT * HD / 8; u += 256) {
        int t = (u * 8) >> 6, d = (u * 8) & 63;
        CP16(sK_u32 + (uint32_t)(t * SKP + d) * 2, g_Kh + base + (size_t)u * 8);
    }
    CP_COMMIT();
    for (int idx = tid; idx < TT * HD; idx += 256) {
        int t = idx >> 6, d = idx & 63;
        sVt[d * VTP + t] = g_Vh[base + idx];
    }
    CP_WAIT0();
    __syncthreads();

    const int win = bx >> 4, h = bx & 15;

#pragma unroll 1
    for (int rb = 0; rb < 2; ++rb) {
        const int r0 = wq * 32 + rb * 16;
        uint32_t qa[4][4];
#pragma unroll
        for (int kc = 0; kc < 4; ++kc) {
            const __half* q0 = g_Qh + base + (size_t)(r0 + grp) * HD + kc * 16;
            const __half* q1 = g_Qh + base + (size_t)(r0 + grp + 8) * HD + kc * 16;
            qa[kc][0] = *reinterpret_cast<const uint32_t*>(q0 + 2 * tig);
            qa[kc][1] = *reinterpret_cast<const uint32_t*>(q1 + 2 * tig);
            qa[kc][2] = *reinterpret_cast<const uint32_t*>(q0 + 8 + 2 * tig);
            qa[kc][3] = *reinterpret_cast<const uint32_t*>(q1 + 8 + 2 * tig);
        }

        float m_lo = -1e30f, m_hi = -1e30f, l_lo = 0.0f, l_hi = 0.0f;
        float O[8][4];
#pragma unroll
        for (int vt = 0; vt < 8; ++vt)
#pragma unroll
            for (int j = 0; j < 4; ++j) O[vt][j] = 0.0f;

#pragma unroll 1
        for (int ch = 0; ch < 4; ++ch) {         // 64 keys per chunk; scores in log2 units
            float S[8][4];
#pragma unroll
            for (int nt = 0; nt < 8; ++nt)
#pragma unroll
                for (int j = 0; j < 4; ++j) S[nt][j] = 0.0f;

#pragma unroll
            for (int kc = 0; kc < 4; ++kc) {
                const int kw = kc * 8 + tig;
#pragma unroll
                for (int nt = 0; nt < 8; ++nt) {
                    const int key = ch * 64 + nt * 8 + grp;
                    uint32_t b0 = sK32[key * (SKP / 2) + kw];
                    uint32_t b1 = sK32[key * (SKP / 2) + kw + 4];
                    mma_fp16(S[nt], qa[kc], b0, b1);
                }
            }
            float cx_lo = -1e30f, cx_hi = -1e30f;
#pragma unroll
            for (int nt = 0; nt < 8; ++nt) {
                cx_lo = fmaxf(cx_lo, fmaxf(S[nt][0], S[nt][1]));
                cx_hi = fmaxf(cx_hi, fmaxf(S[nt][2], S[nt][3]));
            }
            cx_lo = fmaxf(cx_lo, __shfl_xor_sync(0xffffffff, cx_lo, 1));
            cx_lo = fmaxf(cx_lo, __shfl_xor_sync(0xffffffff, cx_lo, 2));
            cx_hi = fmaxf(cx_hi, __shfl_xor_sync(0xffffffff, cx_hi, 1));
            cx_hi = fmaxf(cx_hi, __shfl_xor_sync(0xffffffff, cx_hi, 2));

            float mn_lo = fmaxf(m_lo, cx_lo), mn_hi = fmaxf(m_hi, cx_hi);
            float cor_lo = exp2f(m_lo - mn_lo), cor_hi = exp2f(m_hi - mn_hi);
            m_lo = mn_lo; m_hi = mn_hi;

            float sum_lo = 0.0f, sum_hi = 0.0f;
#pragma unroll
            for (int nt = 0; nt < 8; ++nt) {
                S[nt][0] = exp2f(S[nt][0] - m_lo);
                S[nt][1] = exp2f(S[nt][1] - m_lo);
                S[nt][2] = exp2f(S[nt][2] - m_hi);
                S[nt][3] = exp2f(S[nt][3] - m_hi);
                sum_lo += S[nt][0] + S[nt][1];
                sum_hi += S[nt][2] + S[nt][3];
            }
            sum_lo += __shfl_xor_sync(0xffffffff, sum_lo, 1);
            sum_lo += __shfl_xor_sync(0xffffffff, sum_lo, 2);
            sum_hi += __shfl_xor_sync(0xffffffff, sum_hi, 1);
            sum_hi += __shfl_xor_sync(0xffffffff, sum_hi, 2);
            l_lo = l_lo * cor_lo + sum_lo;
            l_hi = l_hi * cor_hi + sum_hi;

#pragma unroll
            for (int vt = 0; vt < 8; ++vt) {
                O[vt][0] *= cor_lo; O[vt][1] *= cor_lo;
                O[vt][2] *= cor_hi; O[vt][3] *= cor_hi;
            }

#pragma unroll
            for (int kj = 0; kj < 4; ++kj) {     // 16 keys per A-frag
                uint32_t pa[4];
                pa[0] = packh2(S[2 * kj][0],     S[2 * kj][1]);
                pa[1] = packh2(S[2 * kj][2],     S[2 * kj][3]);
                pa[2] = packh2(S[2 * kj + 1][0], S[2 * kj + 1][1]);
                pa[3] = packh2(S[2 * kj + 1][2], S[2 * kj + 1][3]);
                const int kwv = ch * 32 + kj * 8 + tig;
#pragma unroll
                for (int vt = 0; vt < 8; ++vt) {
                    uint32_t b0 = sVt32[(vt * 8 + grp) * (VTP / 2) + kwv];
                    uint32_t b1 = sVt32[(vt * 8 + grp) * (VTP / 2) + kwv + 4];
                    mma_fp16(O[vt], pa, b0, b1);
                }
            }
        }

        const float inv_lo = 1.0f / l_lo, inv_hi = 1.0f / l_hi;
        const size_t ob_lo = (size_t)(win * TT + r0 + grp) * CD + h * HD;
        const size_t ob_hi = (size_t)(win * TT + r0 + grp + 8) * CD + h * HD;
#pragma unroll
        for (int vt = 0; vt < 8; ++vt) {
            const int c = vt * 8 + 2 * tig;
            *reinterpret_cast<uint32_t*>(g_of + ob_lo + c) =
                packh2(O[vt][0] * inv_lo, O[vt][1] * inv_lo);
            *reinterpret_cast<uint32_t*>(g_of + ob_hi + c) =
                packh2(O[vt][2] * inv_hi, O[vt][3] * inv_hi);
        }
    }
}

// ---------------- launch ----------------
extern "C" void kernel_launch(void* const* d_in, const int* in_sizes, int n_in,
                              void* d_out, int out_size) {
    const float* x     = (const float*)d_in[0];
    // d_in[1] = position_ids (unused: window-local RoPE positions are fixed)
    const float* Wqkv  = (const float*)d_in[2];
    const float* Wproj = (const float*)d_in[3];
    float* out = (float*)d_out;

    cudaFuncSetAttribute(attn_kernel, cudaFuncAttributeMaxDynamicSharedMemorySize, ATTN_SMEM);
    cudaFuncSetAttribute(hmma_gemm_kernel, cudaFuncAttributeMaxDynamicSharedMemorySize, GEMM_SMEM);
    // Opt into max shared-memory carveout so TWO CTAs co-reside per SM
    // (61.4KB*2 = 122.9KB GEMM, 70.7KB*2 = 141.3KB attn; both <= 228KB).
    cudaFuncSetAttribute(hmma_gemm_kernel, cudaFuncAttributePreferredSharedMemoryCarveout, 100);
    cudaFuncSetAttribute(attn_kernel, cudaFuncAttributePreferredSharedMemoryCarveout, 100);

    init_tables_kernel<<<MTOT / 256, 256>>>();
    conv_x_kernel<<<(MTOT * (CD / 8)) / 256, 256>>>(x);
    conv_w_kernel<<<((C3 + CD) * CD / 8) / 256, 256>>>(Wqkv, Wproj);

    dim3 gQKV(C3 / BN, MTOT / BM);    // 24 x 512, fused RoPE/V epilogue
    hmma_gemm_kernel<<<gQKV, 256, GEMM_SMEM>>>(0, nullptr);

    attn_kernel<<<NWIN * NH, 256, ATTN_SMEM>>>();

    dim3 gP(CD / BN, MTOT / BM);      // 8 x 512
    hmma_gemm_kernel<<<gP, 256, GEMM_SMEM>>>(1, out);
}

// round 17
// speedup vs baseline: 1.0155x; 1.0155x over previous
#include <cuda_runtime.h>
#include <cuda_bf16.h>
#include <cuda_fp16.h>
#include <math.h>
#include <stdint.h>

// ---------------- problem constants ----------------
#define BSZ   4
#define GHW   128
#define WS    16
#define TT    256            // tokens per window
#define NWIN  256
#define NH    16
#define HD    64
#define CD    1024
#define C3    3072
#define MTOT  65536          // NWIN * TT
#define QSCALE_E 0.180336880111120430f   // 0.125 * log2(e): scores in base-2 units

// GEMM tile config (HMMA, cp.async 3-stage, BK=32)
#define BM 128
#define BN 128
#define BK 32
#define KP 40                // padded row elems -> 80B rows (ldmatrix conflict-free, R8-proven)
#define KPB 80               // row stride bytes
#define AH_E 0
#define BH_E (128 * KP)
#define STAGE_E (2 * 128 * KP)            // 10240 elems
#define STAGE_B (STAGE_E * 2)             // 20480 bytes
#define NSTAGE 3
#define GEMM_SMEM (NSTAGE * STAGE_B)      // 61440 bytes dynamic

// flash-attention smem layout (halves)
#define SKP   72                          // K row stride (36 words)
#define VTP   264                         // Vt row stride (132 words)
#define ATTN_SMEM ((TT * SKP + HD * VTP) * 2)   // 70656 bytes

// ---------------- scratch (no allocation allowed) ----------------
__device__ __half g_Qh[(size_t)NWIN * NH * TT * HD];
__device__ __half g_Kh[(size_t)NWIN * NH * TT * HD];
__device__ __half g_Vh[(size_t)NWIN * NH * TT * HD];
__device__ __half g_xf[(size_t)MTOT * CD];   // x fp16, window order
__device__ __half g_of[(size_t)MTOT * CD];   // attention out fp16 (proj A)
__device__ __half g_wf[(size_t)C3 * CD];     // Wqkv fp16
__device__ __half g_wpf[(size_t)CD * CD];    // Wproj fp16
__device__ float g_cos[TT * 32];
__device__ float g_sin[TT * 32];
__device__ int   g_xrow[MTOT];

__device__ __forceinline__ int xrow_of_m(int m) {
    int win = m >> 8, t = m & 255;
    int b = win >> 6, wh = (win >> 3) & 7, ww = win & 7;
    int r = t >> 4, c = t & 15;
    return b * (GHW * GHW) + (wh * WS + r) * GHW + (ww * WS + c);
}

__device__ __forceinline__ void mma_fp16(float* c, const uint32_t* a, uint32_t b0, uint32_t b1) {
    asm volatile("mma.sync.aligned.m16n8k16.row.col.f32.f16.f16.f32 "
                 "{%0,%1,%2,%3}, {%4,%5,%6,%7}, {%8,%9}, {%0,%1,%2,%3};"
                 : "+f"(c[0]), "+f"(c[1]), "+f"(c[2]), "+f"(c[3])
                 : "r"(a[0]), "r"(a[1]), "r"(a[2]), "r"(a[3]), "r"(b0), "r"(b1));
}

__device__ __forceinline__ void ldsm4(uint32_t addr, uint32_t* r) {
    asm volatile("ldmatrix.sync.aligned.m8n8.x4.shared.b16 {%0,%1,%2,%3}, [%4];"
                 : "=r"(r[0]), "=r"(r[1]), "=r"(r[2]), "=r"(r[3]) : "r"(addr));
}

__device__ __forceinline__ uint32_t smem_u32(const void* p) {
    uint32_t a;
    asm("{ .reg .u64 t; cvta.to.shared.u64 t, %1; cvt.u32.u64 %0, t; }" : "=r"(a) : "l"(p));
    return a;
}
__device__ __forceinline__ uint32_t packh2(float a, float b) {
    union { __half2 h; uint32_t u; } v;
    v.h = __floats2half2_rn(a, b);
    return v.u;
}

#define CP16(dst, src) \
    asm volatile("cp.async.cg.shared.global [%0], [%1], 16;" :: "r"(dst), "l"(src) : "memory")
#define CP_COMMIT() asm volatile("cp.async.commit_group;" ::: "memory")
#define CP_WAIT1()  asm volatile("cp.async.wait_group 1;" ::: "memory")
#define CP_WAIT0()  asm volatile("cp.async.wait_group 0;" ::: "memory")

// ---------------- init: rope table + gather map ----------------
__global__ void init_tables_kernel() {
    int i = blockIdx.x * 256 + threadIdx.x;
    if (i < MTOT) g_xrow[i] = xrow_of_m(i);
    if (i < TT * 32) {
        int t = i >> 5, j = i & 31;
        int r = t >> 4, c = t & 15;
        float inv = powf(10000.0f, -(float)j / 32.0f);
        float pos = (j < 16) ? (float)r : (float)c;
        g_cos[i] = cosf(pos * inv);
        g_sin[i] = sinf(pos * inv);
    }
}

// ---------------- conversion helpers ----------------
union U4F16 { uint4 u; __half h[8]; };

__device__ __forceinline__ void tof16(const float* v, U4F16& f) {
#pragma unroll
    for (int j = 0; j < 8; ++j) f.h[j] = __float2half(v[j]);
}

__global__ void __launch_bounds__(256) conv_x_kernel(const float* __restrict__ x) {
    int i = blockIdx.x * 256 + threadIdx.x;
    int e0 = i * 8;
    int m = e0 >> 10, k = e0 & 1023;
    int src = xrow_of_m(m);
    float v[8];
    const float4* sp = reinterpret_cast<const float4*>(x + (size_t)src * CD + k);
    float4 a = sp[0], b = sp[1];
    v[0]=a.x; v[1]=a.y; v[2]=a.z; v[3]=a.w; v[4]=b.x; v[5]=b.y; v[6]=b.z; v[7]=b.w;
    U4F16 f; tof16(v, f);
    reinterpret_cast<uint4*>(g_xf + (size_t)m * CD + k)[0] = f.u;
}

// both weight arrays in one launch
__global__ void __launch_bounds__(256) conv_w_kernel(const float* __restrict__ wqkv,
                                                     const float* __restrict__ wproj) {
    int i = blockIdx.x * 256 + threadIdx.x;
    size_t e0 = (size_t)i * 8;
    const float* src; __half* dst;
    if (e0 < (size_t)C3 * CD) { src = wqkv + e0; dst = g_wf + e0; }
    else { src = wproj + (e0 - (size_t)C3 * CD); dst = g_wpf + (e0 - (size_t)C3 * CD); }
    float v[8];
    const float4* sp = reinterpret_cast<const float4*>(src);
    float4 a = sp[0], b = sp[1];
    v[0]=a.x; v[1]=a.y; v[2]=a.z; v[3]=a.w; v[4]=b.x; v[5]=b.y; v[6]=b.z; v[7]=b.w;
    U4F16 f; tof16(v, f);
    reinterpret_cast<uint4*>(dst)[0] = f.u;
}

// ---------------- HMMA fp16 GEMM (BK=32, 3-stage, ldmatrix fragments) ----------
// mode 0: QKV — A=g_xf, B=g_wf (3072 cols), epilogue RoPE(Q,K)+V -> g_Qh/g_Kh/g_Vh
// mode 1: proj — A=g_of, B=g_wpf, scatter rows via g_xrow -> out (fp32)
__global__ void __launch_bounds__(256) hmma_gemm_kernel(int mode, float* __restrict__ out) {
    extern __shared__ __half ts[];

    const char* Ap = (mode == 0) ? (const char*)g_xf : (const char*)g_of;
    const char* Bp = (mode == 0) ? (const char*)g_wf : (const char*)g_wpf;

    const int tid  = threadIdx.x;
    const int wid  = tid >> 5;
    const int lane = tid & 31;
    const int wm   = wid & 3;
    const int wn   = wid >> 2;
    const int grp  = lane >> 2;
    const int tig  = lane & 3;
    const int m0   = blockIdx.y * BM;
    const int n0   = blockIdx.x * BN;

    // staging map (proven): u = tid*2 + j ; row = u>>2, seg = (u&3)*8 elems (16B)
    const int u0 = tid * 2, u1 = tid * 2 + 1;
    const int r0s = u0 >> 2, s0s = (u0 & 3) * 8;
    const int r1s = u1 >> 2, s1s = (u1 & 3) * 8;
    const size_t gA0 = ((size_t)(m0 + r0s) * CD + s0s) * 2;   // byte offsets
    const size_t gA1 = ((size_t)(m0 + r1s) * CD + s1s) * 2;
    const size_t gB0 = ((size_t)(n0 + r0s) * CD + s0s) * 2;
    const size_t gB1 = ((size_t)(n0 + r1s) * CD + s1s) * 2;

    const uint32_t ts_u32 = smem_u32(ts);
    const uint32_t dAH0 = (uint32_t)(AH_E + r0s * KP + s0s) * 2;
    const uint32_t dAH1 = (uint32_t)(AH_E + r1s * KP + s1s) * 2;
    const uint32_t dBH0 = (uint32_t)(BH_E + r0s * KP + s0s) * 2;
    const uint32_t dBH1 = (uint32_t)(BH_E + r1s * KP + s1s) * 2;

    // ldmatrix lane addressing (R8-proven): row select + k-half select
    const uint32_t lrow16 = (uint32_t)(lane & 15) * KPB + (uint32_t)(lane >> 4) * 16;
    const uint32_t aROW = (uint32_t)(wm * 32) * KPB;   // A warp row base (bytes)
    const uint32_t bROW = (uint32_t)(wn * 64) * KPB;   // B warp row base (bytes)

    float C[2][8][4];
#pragma unroll
    for (int a = 0; a < 2; ++a)
#pragma unroll
        for (int n = 0; n < 8; ++n)
#pragma unroll
            for (int j = 0; j < 4; ++j) C[a][n][j] = 0.0f;

    const int NCH = CD / BK;   // 32

    // prologue: stages 0 and 1 in flight (separate commit groups)
    {
        const uint32_t sb0 = ts_u32;
        CP16(sb0 + dAH0, Ap + gA0); CP16(sb0 + dAH1, Ap + gA1);
        CP16(sb0 + dBH0, Bp + gB0); CP16(sb0 + dBH1, Bp + gB1);
        CP_COMMIT();
        const size_t k1 = (size_t)BK * 2;
        const uint32_t sb1 = ts_u32 + STAGE_B;
        CP16(sb1 + dAH0, Ap + gA0 + k1); CP16(sb1 + dAH1, Ap + gA1 + k1);
        CP16(sb1 + dBH0, Bp + gB0 + k1); CP16(sb1 + dBH1, Bp + gB1 + k1);
        CP_COMMIT();
    }

    int stage = 0;
#pragma unroll 1
    for (int c = 0; c < NCH; ++c) {
        if (c + 1 < NCH) { CP_WAIT1(); } else { CP_WAIT0(); }   // stage c retired
        __syncthreads();   // stage c visible; prev compute done (protects c+2 slot)

        if (c + 2 < NCH) {
            const size_t k2 = (size_t)(c + 2) * BK * 2;
            int st2 = stage + 2; if (st2 >= NSTAGE) st2 -= NSTAGE;
            const uint32_t sb = ts_u32 + (uint32_t)st2 * STAGE_B;
            CP16(sb + dAH0, Ap + gA0 + k2); CP16(sb + dAH1, Ap + gA1 + k2);
            CP16(sb + dBH0, Bp + gB0 + k2); CP16(sb + dBH1, Bp + gB1 + k2);
            CP_COMMIT();
        }

        const uint32_t sbb = ts_u32 + (uint32_t)stage * STAGE_B;   // stage byte base
#pragma unroll
        for (int ks = 0; ks < 2; ++ks) {
            const uint32_t kb = (uint32_t)ks * 32;                  // k byte offset
            uint32_t ah[2][4];
#pragma unroll
            for (int a = 0; a < 2; ++a)
                ldsm4(sbb + (AH_E * 2) + aROW + (uint32_t)(a * 16) * KPB + lrow16 + kb, ah[a]);
#pragma unroll
            for (int ntp = 0; ntp < 4; ++ntp) {                     // covers nt=2ntp, 2ntp+1
                uint32_t q[4];
                ldsm4(sbb + (BH_E * 2) + bROW + (uint32_t)(ntp * 16) * KPB + lrow16 + kb, q);
                const int n0t = 2 * ntp, n1t = 2 * ntp + 1;
#pragma unroll
                for (int a = 0; a < 2; ++a) {
                    mma_fp16(C[a][n0t], ah[a], q[0], q[2]);
                    mma_fp16(C[a][n1t], ah[a], q[1], q[3]);
                }
            }
        }
        if (++stage == NSTAGE) stage = 0;
    }

    // ---------------- epilogue ----------------
#pragma unroll
    for (int a = 0; a < 2; ++a) {
#pragma unroll
        for (int nt = 0; nt < 8; ++nt) {
            const int col = n0 + wn * 64 + nt * 8 + 2 * tig;
#pragma unroll
            for (int half = 0; half < 2; ++half) {
                const int row = m0 + wm * 32 + a * 16 + grp + half * 8;
                float v0 = C[a][nt][half * 2 + 0];
                float v1 = C[a][nt][half * 2 + 1];
                if (mode == 0) {
                    const int t = row & 255, win = row >> 8;
                    const int s = col >> 10;                 // 0=Q, 1=K, 2=V
                    const int h = (col & 1023) >> 6;
                    const int d = col & 63;                  // even
                    float o0, o1;
                    if (s < 2) {
                        const int p = d >> 1;
                        float cc = g_cos[t * 32 + p], ss = g_sin[t * 32 + p];
                        o0 = v0 * cc - v1 * ss;
                        o1 = v0 * ss + v1 * cc;
                        if (s == 0) { o0 *= QSCALE_E; o1 *= QSCALE_E; }
                    } else { o0 = v0; o1 = v1; }
                    __half* dst = (s == 0) ? g_Qh : (s == 1) ? g_Kh : g_Vh;
                    const size_t base = (((size_t)(win * NH + h)) * TT + t) * (size_t)HD + d;
                    *reinterpret_cast<uint32_t*>(dst + base) = packh2(o0, o1);
                } else {
                    const size_t orow = (size_t)g_xrow[row];
                    *reinterpret_cast<float2*>(out + orow * CD + col) = make_float2(v0, v1);
                }
            }
        }
    }
}

// ---------------- HMMA flash-attention: one CTA per (win, head), base-2 softmax ----------
__global__ void __launch_bounds__(256) attn_kernel() {
    extern __shared__ __half sma[];
    __half* sK  = sma;                    // [256][72]
    __half* sVt = sma + TT * SKP;         // [64][264]
    const uint32_t* sK32  = reinterpret_cast<const uint32_t*>(sK);
    const uint32_t* sVt32 = reinterpret_cast<const uint32_t*>(sVt);
    const uint32_t sK_u32 = smem_u32(sK);

    const int bx  = blockIdx.x;           // win*16 + h
    const int tid = threadIdx.x;
    const int wq  = tid >> 5;
    const int lane = tid & 31;
    const int grp = lane >> 2, tig = lane & 3;
    const size_t base = (size_t)bx * TT * HD;

    // K via cp.async (8 x 16B per thread), V transpose scalar in the shadow
    for (int u = tid; u < TT * HD / 8; u += 256) {
        int t = (u * 8) >> 6, d = (u * 8) & 63;
        CP16(sK_u32 + (uint32_t)(t * SKP + d) * 2, g_Kh + base + (size_t)u * 8);
    }
    CP_COMMIT();
    for (int idx = tid; idx < TT * HD; idx += 256) {
        int t = idx >> 6, d = idx & 63;
        sVt[d * VTP + t] = g_Vh[base + idx];
    }
    CP_WAIT0();
    __syncthreads();

    const int win = bx >> 4, h = bx & 15;

#pragma unroll 1
    for (int rb = 0; rb < 2; ++rb) {
        const int r0 = wq * 32 + rb * 16;
        uint32_t qa[4][4];
#pragma unroll
        for (int kc = 0; kc < 4; ++kc) {
            const __half* q0 = g_Qh + base + (size_t)(r0 + grp) * HD + kc * 16;
            const __half* q1 = g_Qh + base + (size_t)(r0 + grp + 8) * HD + kc * 16;
            qa[kc][0] = *reinterpret_cast<const uint32_t*>(q0 + 2 * tig);
            qa[kc][1] = *reinterpret_cast<const uint32_t*>(q1 + 2 * tig);
            qa[kc][2] = *reinterpret_cast<const uint32_t*>(q0 + 8 + 2 * tig);
            qa[kc][3] = *reinterpret_cast<const uint32_t*>(q1 + 8 + 2 * tig);
        }

        float m_lo = -1e30f, m_hi = -1e30f, l_lo = 0.0f, l_hi = 0.0f;
        float O[8][4];
#pragma unroll
        for (int vt = 0; vt < 8; ++vt)
#pragma unroll
            for (int j = 0; j < 4; ++j) O[vt][j] = 0.0f;

#pragma unroll 1
        for (int ch = 0; ch < 4; ++ch) {         // 64 keys per chunk; scores in log2 units
            float S[8][4];
#pragma unroll
            for (int nt = 0; nt < 8; ++nt)
#pragma unroll
                for (int j = 0; j < 4; ++j) S[nt][j] = 0.0f;

#pragma unroll
            for (int kc = 0; kc < 4; ++kc) {
                const int kw = kc * 8 + tig;
#pragma unroll
                for (int nt = 0; nt < 8; ++nt) {
                    const int key = ch * 64 + nt * 8 + grp;
                    uint32_t b0 = sK32[key * (SKP / 2) + kw];
                    uint32_t b1 = sK32[key * (SKP / 2) + kw + 4];
                    mma_fp16(S[nt], qa[kc], b0, b1);
                }
            }
            float cx_lo = -1e30f, cx_hi = -1e30f;
#pragma unroll
            for (int nt = 0; nt < 8; ++nt) {
                cx_lo = fmaxf(cx_lo, fmaxf(S[nt][0], S[nt][1]));
                cx_hi = fmaxf(cx_hi, fmaxf(S[nt][2], S[nt][3]));
            }
            cx_lo = fmaxf(cx_lo, __shfl_xor_sync(0xffffffff, cx_lo, 1));
            cx_lo = fmaxf(cx_lo, __shfl_xor_sync(0xffffffff, cx_lo, 2));
            cx_hi = fmaxf(cx_hi, __shfl_xor_sync(0xffffffff, cx_hi, 1));
            cx_hi = fmaxf(cx_hi, __shfl_xor_sync(0xffffffff, cx_hi, 2));

            float mn_lo = fmaxf(m_lo, cx_lo), mn_hi = fmaxf(m_hi, cx_hi);
            float cor_lo = exp2f(m_lo - mn_lo), cor_hi = exp2f(m_hi - mn_hi);
            m_lo = mn_lo; m_hi = mn_hi;

            float sum_lo = 0.0f, sum_hi = 0.0f;
#pragma unroll
            for (int nt = 0; nt < 8; ++nt) {
                S[nt][0] = exp2f(S[nt][0] - m_lo);
                S[nt][1] = exp2f(S[nt][1] - m_lo);
                S[nt][2] = exp2f(S[nt][2] - m_hi);
                S[nt][3] = exp2f(S[nt][3] - m_hi);
                sum_lo += S[nt][0] + S[nt][1];
                sum_hi += S[nt][2] + S[nt][3];
            }
            sum_lo += __shfl_xor_sync(0xffffffff, sum_lo, 1);
            sum_lo += __shfl_xor_sync(0xffffffff, sum_lo, 2);
            sum_hi += __shfl_xor_sync(0xffffffff, sum_hi, 1);
            sum_hi += __shfl_xor_sync(0xffffffff, sum_hi, 2);
            l_lo = l_lo * cor_lo + sum_lo;
            l_hi = l_hi * cor_hi + sum_hi;

#pragma unroll
            for (int vt = 0; vt < 8; ++vt) {
                O[vt][0] *= cor_lo; O[vt][1] *= cor_lo;
                O[vt][2] *= cor_hi; O[vt][3] *= cor_hi;
            }

#pragma unroll
            for (int kj = 0; kj < 4; ++kj) {     // 16 keys per A-frag
                uint32_t pa[4];
                pa[0] = packh2(S[2 * kj][0],     S[2 * kj][1]);
                pa[1] = packh2(S[2 * kj][2],     S[2 * kj][3]);
                pa[2] = packh2(S[2 * kj + 1][0], S[2 * kj + 1][1]);
                pa[3] = packh2(S[2 * kj + 1][2], S[2 * kj + 1][3]);
                const int kwv = ch * 32 + kj * 8 + tig;
#pragma unroll
                for (int vt = 0; vt < 8; ++vt) {
                    uint32_t b0 = sVt32[(vt * 8 + grp) * (VTP / 2) + kwv];
                    uint32_t b1 = sVt32[(vt * 8 + grp) * (VTP / 2) + kwv + 4];
                    mma_fp16(O[vt], pa, b0, b1);
                }
            }
        }

        const float inv_lo = 1.0f / l_lo, inv_hi = 1.0f / l_hi;
        const size_t ob_lo = (size_t)(win * TT + r0 + grp) * CD + h * HD;
        const size_t ob_hi = (size_t)(win * TT + r0 + grp + 8) * CD + h * HD;
#pragma unroll
        for (int vt = 0; vt < 8; ++vt) {
            const int c = vt * 8 + 2 * tig;
            *reinterpret_cast<uint32_t*>(g_of + ob_lo + c) =
                packh2(O[vt][0] * inv_lo, O[vt][1] * inv_lo);
            *reinterpret_cast<uint32_t*>(g_of + ob_hi + c) =
                packh2(O[vt][2] * inv_hi, O[vt][3] * inv_hi);
        }
    }
}

// ---------------- launch ----------------
extern "C" void kernel_launch(void* const* d_in, const int* in_sizes, int n_in,
                              void* d_out, int out_size) {
    const float* x     = (const float*)d_in[0];
    // d_in[1] = position_ids (unused: window-local RoPE positions are fixed)
    const float* Wqkv  = (const float*)d_in[2];
    const float* Wproj = (const float*)d_in[3];
    float* out = (float*)d_out;

    cudaFuncSetAttribute(attn_kernel, cudaFuncAttributeMaxDynamicSharedMemorySize, ATTN_SMEM);
    cudaFuncSetAttribute(hmma_gemm_kernel, cudaFuncAttributeMaxDynamicSharedMemorySize, GEMM_SMEM);

    init_tables_kernel<<<MTOT / 256, 256>>>();
    conv_x_kernel<<<(MTOT * (CD / 8)) / 256, 256>>>(x);
    conv_w_kernel<<<((C3 + CD) * CD / 8) / 256, 256>>>(Wqkv, Wproj);

    dim3 gQKV(C3 / BN, MTOT / BM);    // 24 x 512, fused RoPE/V epilogue
    hmma_gemm_kernel<<<gQKV, 256, GEMM_SMEM>>>(0, nullptr);

    attn_kernel<<<NWIN * NH, 256, ATTN_SMEM>>>();

    dim3 gP(CD / BN, MTOT / BM);      // 8 x 512
    hmma_gemm_kernel<<<gP, 256, GEMM_SMEM>>>(1, out);
}